// round 1
// baseline (speedup 1.0000x reference)
#include <cuda_runtime.h>

// Per-image mean scratch (batch is 256 in this problem; sized generously).
#define MAX_B 1024
__device__ float g_mean[MAX_B];

#define MAGS_PER_TF 9

// ---------------------------------------------------------------------------
// Kernel A: per-image mean, computed ONLY for images that will apply the
// contrast transform (tf_idx == 1 && apply_mask[sample] > 0). One block per
// image; float4 loads; warp-shuffle + smem block reduction.
// ---------------------------------------------------------------------------
__global__ void mean_kernel(const float4* __restrict__ x,
                            const int* __restrict__ sample,
                            const int* __restrict__ apply_mask,
                            int vec_per_img)
{
    const int b = blockIdx.x;
    const int s = __ldg(&sample[b]);
    const int tf = s / MAGS_PER_TF;
    const bool need = (tf == 1) && (__ldg(&apply_mask[s]) > 0);

    if (!need) {
        if (threadIdx.x == 0) g_mean[b] = 0.0f;
        return;  // skip the read entirely
    }

    const float4* img = x + (size_t)b * vec_per_img;
    float acc = 0.0f;
    for (int i = threadIdx.x; i < vec_per_img; i += blockDim.x) {
        float4 v = img[i];
        acc += (v.x + v.y) + (v.z + v.w);
    }

    // warp reduce
    #pragma unroll
    for (int off = 16; off > 0; off >>= 1)
        acc += __shfl_xor_sync(0xFFFFFFFFu, acc, off);

    __shared__ float warp_sums[32];
    const int lane = threadIdx.x & 31;
    const int wid  = threadIdx.x >> 5;
    if (lane == 0) warp_sums[wid] = acc;
    __syncthreads();

    if (wid == 0) {
        const int nwarps = (blockDim.x + 31) >> 5;
        float v = (lane < nwarps) ? warp_sums[lane] : 0.0f;
        #pragma unroll
        for (int off = 16; off > 0; off >>= 1)
            v += __shfl_xor_sync(0xFFFFFFFFu, v, off);
        if (lane == 0)
            g_mean[b] = v / (float)(vec_per_img * 4);
    }
}

// ---------------------------------------------------------------------------
// Kernel B: out = saturate(alpha[b] * x + beta[b]), float4 vectorized.
// alpha/beta derived per block from (sample, apply_mask, mean).
// ---------------------------------------------------------------------------
__global__ void apply_kernel(const float4* __restrict__ x,
                             const int* __restrict__ sample,
                             const int* __restrict__ apply_mask,
                             float4* __restrict__ out,
                             int vec_per_img)
{
    const int b = blockIdx.y;
    const int i = blockIdx.x * blockDim.x + threadIdx.x;

    const int s = __ldg(&sample[b]);
    const int tf = s / MAGS_PER_TF;
    const float mag = (float)(s % MAGS_PER_TF + 1) / 10.0f;
    const bool applied = (__ldg(&apply_mask[s]) > 0);

    float alpha = 1.0f, beta = 0.0f;
    if (applied) {
        if (tf == 0) {                 // brightness: x + mag
            alpha = 1.0f;        beta = mag;
        } else if (tf == 1) {          // contrast: mean + (x-mean)*(1+mag)
            const float m = g_mean[b];
            alpha = 1.0f + mag;  beta = -m * mag;
        } else if (tf == 2) {          // invert blend: (1-2mag)*x + mag
            alpha = 1.0f - 2.0f * mag; beta = mag;
        } else {                       // gain: x*(1+mag)
            alpha = 1.0f + mag;  beta = 0.0f;
        }
    }

    if (i < vec_per_img) {
        const size_t idx = (size_t)b * vec_per_img + i;
        float4 v = x[idx];
        v.x = __saturatef(fmaf(alpha, v.x, beta));
        v.y = __saturatef(fmaf(alpha, v.y, beta));
        v.z = __saturatef(fmaf(alpha, v.z, beta));
        v.w = __saturatef(fmaf(alpha, v.w, beta));
        out[idx] = v;
    }
}

// ---------------------------------------------------------------------------
// Launch. Inputs per metadata order: x (float32), sample (int32),
// apply_mask (int32). Output float32, same shape as x.
// ---------------------------------------------------------------------------
extern "C" void kernel_launch(void* const* d_in, const int* in_sizes, int n_in,
                              void* d_out, int out_size)
{
    const float* x          = (const float*)d_in[0];
    const int*   sample     = (const int*)d_in[1];
    const int*   apply_mask = (const int*)d_in[2];
    float*       out        = (float*)d_out;

    const int B = in_sizes[1];                 // 256
    const int elems_per_img = in_sizes[0] / B; // 3*224*224 = 150528
    const int vec_per_img = elems_per_img / 4; // 37632 (divisible by 4)

    // Pass 1: conditional per-image mean
    mean_kernel<<<B, 512>>>((const float4*)x, sample, apply_mask, vec_per_img);

    // Pass 2: streaming affine+clamp
    const int threads = 256;
    dim3 grid((vec_per_img + threads - 1) / threads, B);
    apply_kernel<<<grid, threads>>>((const float4*)x, sample, apply_mask,
                                    (float4*)out, vec_per_img);
}

// round 2
// speedup vs baseline: 1.5242x; 1.5242x over previous
#include <cuda_runtime.h>

#define MAX_B 1024
__device__ float g_sum[MAX_B];

#define MAGS_PER_TF 9
#define MEAN_CHUNKS 16

// ---------------------------------------------------------------------------
// Kernel 0: zero the per-image accumulators (trivial).
// ---------------------------------------------------------------------------
__global__ void zero_kernel(int B)
{
    int i = blockIdx.x * blockDim.x + threadIdx.x;
    if (i < B) g_sum[i] = 0.0f;
}

// ---------------------------------------------------------------------------
// Kernel 1: partial per-image sums, ONLY for images applying contrast.
// MEAN_CHUNKS blocks per image; atomicAdd partials into g_sum[b].
// ---------------------------------------------------------------------------
__global__ void mean_kernel(const float4* __restrict__ x,
                            const int* __restrict__ sample,
                            const int* __restrict__ apply_mask,
                            int vec_per_img)
{
    const int b     = blockIdx.x;
    const int chunk = blockIdx.y;

    const int s  = __ldg(&sample[b]);
    const int tf = s / MAGS_PER_TF;
    if (!((tf == 1) && (__ldg(&apply_mask[s]) > 0))) return;  // skip read

    const int chunk_vecs = (vec_per_img + MEAN_CHUNKS - 1) / MEAN_CHUNKS;
    const int start = chunk * chunk_vecs;
    const int end   = min(start + chunk_vecs, vec_per_img);

    const float4* img = x + (size_t)b * vec_per_img;
    float acc = 0.0f;
    for (int i = start + threadIdx.x; i < end; i += blockDim.x) {
        float4 v = __ldcs(&img[i]);
        acc += (v.x + v.y) + (v.z + v.w);
    }

    #pragma unroll
    for (int off = 16; off > 0; off >>= 1)
        acc += __shfl_xor_sync(0xFFFFFFFFu, acc, off);

    __shared__ float warp_sums[32];
    const int lane = threadIdx.x & 31;
    const int wid  = threadIdx.x >> 5;
    if (lane == 0) warp_sums[wid] = acc;
    __syncthreads();

    if (wid == 0) {
        const int nwarps = (blockDim.x + 31) >> 5;
        float v = (lane < nwarps) ? warp_sums[lane] : 0.0f;
        #pragma unroll
        for (int off = 16; off > 0; off >>= 1)
            v += __shfl_xor_sync(0xFFFFFFFFu, v, off);
        if (lane == 0)
            atomicAdd(&g_sum[b], v);
    }
}

// ---------------------------------------------------------------------------
// Kernel 2: out = saturate(alpha[b]*x + beta[b]), 2x float4 per thread,
// streaming loads/stores (no L2 retention needed for the bulk data).
// ---------------------------------------------------------------------------
__global__ void apply_kernel(const float4* __restrict__ x,
                             const int* __restrict__ sample,
                             const int* __restrict__ apply_mask,
                             float4* __restrict__ out,
                             int vec_per_img)
{
    const int b = blockIdx.y;

    const int s  = __ldg(&sample[b]);
    const int tf = s / MAGS_PER_TF;
    const float mag = (float)(s % MAGS_PER_TF + 1) * 0.1f;
    const bool applied = (__ldg(&apply_mask[s]) > 0);

    float alpha = 1.0f, beta = 0.0f;
    if (applied) {
        if (tf == 0) {                       // brightness
            beta = mag;
        } else if (tf == 1) {                // contrast
            const float m = g_sum[b] / (float)(vec_per_img * 4);
            alpha = 1.0f + mag;  beta = -m * mag;
        } else if (tf == 2) {                // invert blend
            alpha = 1.0f - 2.0f * mag; beta = mag;
        } else {                             // gain
            alpha = 1.0f + mag;
        }
    }

    const int base = (blockIdx.x * blockDim.x) * 2 + threadIdx.x;
    const size_t img_off = (size_t)b * vec_per_img;

    const int i0 = base;
    const int i1 = base + blockDim.x;

    float4 v0, v1;
    bool p0 = (i0 < vec_per_img);
    bool p1 = (i1 < vec_per_img);
    if (p0) v0 = __ldcs(&x[img_off + i0]);
    if (p1) v1 = __ldcs(&x[img_off + i1]);

    if (p0) {
        v0.x = __saturatef(fmaf(alpha, v0.x, beta));
        v0.y = __saturatef(fmaf(alpha, v0.y, beta));
        v0.z = __saturatef(fmaf(alpha, v0.z, beta));
        v0.w = __saturatef(fmaf(alpha, v0.w, beta));
        __stcs(&out[img_off + i0], v0);
    }
    if (p1) {
        v1.x = __saturatef(fmaf(alpha, v1.x, beta));
        v1.y = __saturatef(fmaf(alpha, v1.y, beta));
        v1.z = __saturatef(fmaf(alpha, v1.z, beta));
        v1.w = __saturatef(fmaf(alpha, v1.w, beta));
        __stcs(&out[img_off + i1], v1);
    }
}

// ---------------------------------------------------------------------------
extern "C" void kernel_launch(void* const* d_in, const int* in_sizes, int n_in,
                              void* d_out, int out_size)
{
    const float* x          = (const float*)d_in[0];
    const int*   sample     = (const int*)d_in[1];
    const int*   apply_mask = (const int*)d_in[2];
    float*       out        = (float*)d_out;

    const int B = in_sizes[1];                 // 256
    const int elems_per_img = in_sizes[0] / B; // 150528
    const int vec_per_img = elems_per_img / 4; // 37632

    zero_kernel<<<(B + 255) / 256, 256>>>(B);

    dim3 mgrid(B, MEAN_CHUNKS);
    mean_kernel<<<mgrid, 256>>>((const float4*)x, sample, apply_mask, vec_per_img);

    const int threads = 256;
    const int vec_per_block = threads * 2;
    dim3 grid((vec_per_img + vec_per_block - 1) / vec_per_block, B);
    apply_kernel<<<grid, threads>>>((const float4*)x, sample, apply_mask,
                                    (float4*)out, vec_per_img);
}

// round 3
// speedup vs baseline: 1.5438x; 1.0128x over previous
#include <cuda_runtime.h>

#define MAX_B 1024
#define MEAN_CHUNKS 16
#define MAGS_PER_TF 9

// Per-image per-chunk partial sums. Written unconditionally by every mean
// block that does work (contrast images only); read only for those same
// images. No zeroing, no atomics needed.
__device__ float g_part[MAX_B * MEAN_CHUNKS];

// ---------------------------------------------------------------------------
// Kernel 1: partial per-image sums, ONLY for images applying contrast.
// ---------------------------------------------------------------------------
__global__ void mean_kernel(const float4* __restrict__ x,
                            const int* __restrict__ sample,
                            const int* __restrict__ apply_mask,
                            int vec_per_img)
{
    const int b     = blockIdx.x;
    const int chunk = blockIdx.y;

    const int s  = __ldg(&sample[b]);
    const int tf = s / MAGS_PER_TF;
    if (!((tf == 1) && (__ldg(&apply_mask[s]) > 0))) return;  // skip the read

    const int chunk_vecs = (vec_per_img + MEAN_CHUNKS - 1) / MEAN_CHUNKS;
    const int start = chunk * chunk_vecs;
    const int end   = min(start + chunk_vecs, vec_per_img);

    const float4* img = x + (size_t)b * vec_per_img;
    float acc = 0.0f;
    for (int i = start + threadIdx.x; i < end; i += blockDim.x) {
        float4 v = __ldcs(&img[i]);
        acc += (v.x + v.y) + (v.z + v.w);
    }

    #pragma unroll
    for (int off = 16; off > 0; off >>= 1)
        acc += __shfl_xor_sync(0xFFFFFFFFu, acc, off);

    __shared__ float warp_sums[32];
    const int lane = threadIdx.x & 31;
    const int wid  = threadIdx.x >> 5;
    if (lane == 0) warp_sums[wid] = acc;
    __syncthreads();

    if (wid == 0) {
        const int nwarps = (blockDim.x + 31) >> 5;
        float v = (lane < nwarps) ? warp_sums[lane] : 0.0f;
        #pragma unroll
        for (int off = 16; off > 0; off >>= 1)
            v += __shfl_xor_sync(0xFFFFFFFFu, v, off);
        if (lane == 0)
            g_part[b * MEAN_CHUNKS + chunk] = v;
    }
}

// ---------------------------------------------------------------------------
// Kernel 2: out = saturate(alpha[b]*x + beta[b]), 4x float4 per thread,
// front-batched loads for MLP, streaming cache hints.
// ---------------------------------------------------------------------------
#define APPLY_VPT 4   // float4 vectors per thread

__global__ void __launch_bounds__(256)
apply_kernel(const float4* __restrict__ x,
             const int* __restrict__ sample,
             const int* __restrict__ apply_mask,
             float4* __restrict__ out,
             int vec_per_img)
{
    const int b = blockIdx.y;

    const int s  = __ldg(&sample[b]);
    const int tf = s / MAGS_PER_TF;
    const float mag = (float)(s % MAGS_PER_TF + 1) * 0.1f;
    const bool applied = (__ldg(&apply_mask[s]) > 0);

    float alpha = 1.0f, beta = 0.0f;
    if (applied) {
        if (tf == 0) {                       // brightness
            beta = mag;
        } else if (tf == 1) {                // contrast: mean + (x-mean)*(1+mag)
            float sum = 0.0f;
            #pragma unroll
            for (int c = 0; c < MEAN_CHUNKS; c++)
                sum += __ldg(&g_part[b * MEAN_CHUNKS + c]);
            const float m = sum / (float)(vec_per_img * 4);
            alpha = 1.0f + mag;  beta = -m * mag;
        } else if (tf == 2) {                // invert blend
            alpha = 1.0f - 2.0f * mag; beta = mag;
        } else {                             // gain
            alpha = 1.0f + mag;
        }
    }

    const int base = (blockIdx.x * blockDim.x) * APPLY_VPT + threadIdx.x;
    const size_t img_off = (size_t)b * vec_per_img;

    int   idx[APPLY_VPT];
    bool  pred[APPLY_VPT];
    float4 v[APPLY_VPT];

    #pragma unroll
    for (int k = 0; k < APPLY_VPT; k++) {
        idx[k]  = base + k * blockDim.x;
        pred[k] = (idx[k] < vec_per_img);
    }
    // Front-batched loads (MLP)
    #pragma unroll
    for (int k = 0; k < APPLY_VPT; k++)
        if (pred[k]) v[k] = __ldcs(&x[img_off + idx[k]]);

    #pragma unroll
    for (int k = 0; k < APPLY_VPT; k++) {
        if (pred[k]) {
            v[k].x = __saturatef(fmaf(alpha, v[k].x, beta));
            v[k].y = __saturatef(fmaf(alpha, v[k].y, beta));
            v[k].z = __saturatef(fmaf(alpha, v[k].z, beta));
            v[k].w = __saturatef(fmaf(alpha, v[k].w, beta));
            __stcs(&out[img_off + idx[k]], v[k]);
        }
    }
}

// ---------------------------------------------------------------------------
extern "C" void kernel_launch(void* const* d_in, const int* in_sizes, int n_in,
                              void* d_out, int out_size)
{
    const float* x          = (const float*)d_in[0];
    const int*   sample     = (const int*)d_in[1];
    const int*   apply_mask = (const int*)d_in[2];
    float*       out        = (float*)d_out;

    const int B = in_sizes[1];                 // 256
    const int elems_per_img = in_sizes[0] / B; // 150528
    const int vec_per_img = elems_per_img / 4; // 37632

    // Pass 1: conditional per-image partial sums (no zeroing needed)
    dim3 mgrid(B, MEAN_CHUNKS);
    mean_kernel<<<mgrid, 256>>>((const float4*)x, sample, apply_mask, vec_per_img);

    // Pass 2: streaming affine+clamp
    const int threads = 256;
    const int vec_per_block = threads * APPLY_VPT;
    dim3 grid((vec_per_img + vec_per_block - 1) / vec_per_block, B);
    apply_kernel<<<grid, threads>>>((const float4*)x, sample, apply_mask,
                                    (float4*)out, vec_per_img);
}